// round 1
// baseline (speedup 1.0000x reference)
#include <cuda_runtime.h>
#include <cuda_bf16.h>
#include <cstdint>
#include <cstddef>

// ---------------- problem constants ----------------
#define BSZ   4
#define SEQ   128
#define TOK   (BSZ*SEQ)        // 512
#define DM    256
#define NH    4
#define HD    64
#define FF    2048
#define PP    224              // P = 32*7
#define PED   512
#define RR    16
#define PEROW (PP*PED)         // 114688
#define HID   4096
#define KVD   1024
#define INTER 11008

// output region sizes (floats)
#define SZ_AHID (4LL*192*16*4096)     // 50331648
#define SZ_AINT (4LL*32*16*11008)     // 22544384
#define SZ_BHID (4LL*96*4096*16)      // 25165824
#define SZ_BKV  (4LL*64*1024*16)      // 4194304
#define OFF_AINT (SZ_AHID)
#define OFF_BHID (SZ_AHID+SZ_AINT)
#define OFF_BKV  (OFF_BHID+SZ_BHID)
#define OFF_BINT (OFF_BKV+SZ_BKV)

// ---------------- scratch ----------------
#define S_X     0
#define S_QKV   (S_X    + TOK*DM)          // 131072
#define S_ATTN  (S_QKV  + TOK*3*DM)        // +393216
#define S_FF1   (S_ATTN + TOK*DM)          // +131072
#define S_TMP   (S_FF1  + TOK*FF)          // +1048576 (scores 16*128*128 / residual tmp)
#define S_POOL  (S_TMP  + 16*128*128)      // +262144
#define S_PE    (S_POOL + BSZ*DM)          // +1024
#define S_DECH  (S_PE   + BSZ*PEROW)       // +458752
#define S_AB    (S_DECH + 896*DM)          // +229376
#define S_BB    (S_AB   + 896*1024)        // +917504
#define S_PART  (S_BB   + 896*1024)        // +917504
#define S_TOTAL (S_PART + 8*TOK*DM)        // +1048576  => 5538816 floats

__device__ float g_scratch[S_TOTAL];

// ---------------- kernels ----------------

__global__ void embed_kernel(const int* __restrict__ ids, const float* __restrict__ E,
                             float* __restrict__ x) {
    int tok = blockIdx.x;                 // 512
    int t = threadIdx.x;                  // 64
    int id = ids[tok];
    reinterpret_cast<float4*>(x)[tok*64 + t] =
        reinterpret_cast<const float4*>(E)[(size_t)id*64 + t];
}

// C[m,n] = epi( sum_k X[m,k]*W[n,k] + bias[n] ).  64x64 tile, BK=16, 256 thr, 4x4/thr.
// gridDim.z>1 => split-K partials (no bias/epi) into Cpart.
template<int EPI>
__global__ void gemm_nt(const float* __restrict__ X, const float* __restrict__ W,
                        const float* __restrict__ bias, float* __restrict__ C,
                        float* __restrict__ Cpart, int M, int N, int K) {
    __shared__ __align__(16) float Xs[16][64];
    __shared__ __align__(16) float Ws[16][64];
    int tid = threadIdx.x;
    int tx = tid & 15, ty = tid >> 4;
    int m0 = blockIdx.y * 64, n0 = blockIdx.x * 64;
    int kchunk = K / gridDim.z;
    int kbeg = blockIdx.z * kchunk;
    int nk = kchunk >> 4;
    int lr = tid >> 2;                    // 0..63
    int lq = tid & 3;                     // 0..3
    const float* xp = X + (size_t)(m0 + lr) * K + kbeg + lq * 4;
    const float* wp = W + (size_t)(n0 + lr) * K + kbeg + lq * 4;
    float4 rx = *reinterpret_cast<const float4*>(xp);
    float4 rw = *reinterpret_cast<const float4*>(wp);
    float acc[4][4] = {};
    for (int kt = 0; kt < nk; ++kt) {
        Xs[lq*4+0][lr] = rx.x; Xs[lq*4+1][lr] = rx.y;
        Xs[lq*4+2][lr] = rx.z; Xs[lq*4+3][lr] = rx.w;
        Ws[lq*4+0][lr] = rw.x; Ws[lq*4+1][lr] = rw.y;
        Ws[lq*4+2][lr] = rw.z; Ws[lq*4+3][lr] = rw.w;
        __syncthreads();
        if (kt + 1 < nk) {
            rx = *reinterpret_cast<const float4*>(xp + (kt+1)*16);
            rw = *reinterpret_cast<const float4*>(wp + (kt+1)*16);
        }
        #pragma unroll
        for (int k = 0; k < 16; ++k) {
            float4 a = *reinterpret_cast<const float4*>(&Xs[k][ty*4]);
            float4 b = *reinterpret_cast<const float4*>(&Ws[k][tx*4]);
            float av[4] = {a.x, a.y, a.z, a.w};
            float bv[4] = {b.x, b.y, b.z, b.w};
            #pragma unroll
            for (int i = 0; i < 4; ++i)
                #pragma unroll
                for (int j = 0; j < 4; ++j)
                    acc[i][j] += av[i] * bv[j];
        }
        __syncthreads();
    }
    if (gridDim.z == 1) {
        #pragma unroll
        for (int i = 0; i < 4; ++i) {
            int m = m0 + ty*4 + i;
            #pragma unroll
            for (int j = 0; j < 4; ++j) {
                int n = n0 + tx*4 + j;
                float v = acc[i][j] + bias[n];
                if (EPI == 1) v = fmaxf(v, 0.f);
                if (EPI == 2) v = 0.5f * v * (1.f + erff(v * 0.70710678118654752f));
                C[(size_t)m * N + n] = v;
            }
        }
    } else {
        float* P = Cpart + (size_t)blockIdx.z * M * N;
        #pragma unroll
        for (int i = 0; i < 4; ++i)
            #pragma unroll
            for (int j = 0; j < 4; ++j)
                P[(size_t)(m0 + ty*4 + i) * N + n0 + tx*4 + j] = acc[i][j];
    }
}

__global__ void ksplit_reduce(const float* __restrict__ P, const float* __restrict__ bias,
                              float* __restrict__ C, int MN, int N, int parts) {
    int i = blockIdx.x * 256 + threadIdx.x;
    if (i >= MN) return;
    float s = bias[i % N];
    for (int p = 0; p < parts; ++p) s += P[(size_t)p * MN + i];
    C[i] = s;
}

__global__ void attn_scores(const float* __restrict__ qkv, const int* __restrict__ mask,
                            float* __restrict__ sc) {
    int qi = blockIdx.x;               // 128
    int bh = blockIdx.y;               // 16
    int b = bh >> 2, h = bh & 3;
    int t = threadIdx.x;               // 128
    __shared__ __align__(16) float qs[64];
    __shared__ float red[128];
    if (t < 64) qs[t] = qkv[(size_t)(b*128 + qi)*768 + h*64 + t];
    __syncthreads();
    const float4* kp = reinterpret_cast<const float4*>(qkv + (size_t)(b*128 + t)*768 + 256 + h*64);
    float s = 0.f;
    #pragma unroll
    for (int d4 = 0; d4 < 16; ++d4) {
        float4 kv = kp[d4];
        float4 qv = *reinterpret_cast<const float4*>(&qs[d4*4]);
        s += qv.x*kv.x + qv.y*kv.y + qv.z*kv.z + qv.w*kv.w;
    }
    s *= 0.125f;
    if (mask[b*128 + t] == 0) s = -1e9f;
    red[t] = s; __syncthreads();
    for (int st = 64; st > 0; st >>= 1) { if (t < st) red[t] = fmaxf(red[t], red[t+st]); __syncthreads(); }
    float mx = red[0]; __syncthreads();
    float p = __expf(s - mx);
    red[t] = p; __syncthreads();
    for (int st = 64; st > 0; st >>= 1) { if (t < st) red[t] += red[t+st]; __syncthreads(); }
    sc[((size_t)bh*128 + qi)*128 + t] = p / red[0];
}

__global__ void attn_av(const float* __restrict__ qkv, const float* __restrict__ sc,
                        float* __restrict__ o) {
    int qi = blockIdx.x, bh = blockIdx.y;
    int b = bh >> 2, h = bh & 3;
    int t = threadIdx.x;               // 64
    __shared__ float as_[128];
    as_[t]      = sc[((size_t)bh*128 + qi)*128 + t];
    as_[t + 64] = sc[((size_t)bh*128 + qi)*128 + t + 64];
    __syncthreads();
    const float* vp = qkv + 512 + h*64 + t;
    float acc = 0.f;
    #pragma unroll 8
    for (int k = 0; k < 128; ++k) acc += as_[k] * vp[(size_t)(b*128 + k)*768];
    o[(size_t)(b*128 + qi)*256 + h*64 + t] = acc;
}

__global__ void add_ln(float* __restrict__ x, const float* __restrict__ t_,
                       const float* __restrict__ g, const float* __restrict__ b) {
    int row = blockIdx.x;
    int d = threadIdx.x;               // 256
    __shared__ float r1[256], r2[256];
    float h = x[(size_t)row*256 + d] + t_[(size_t)row*256 + d];
    r1[d] = h; r2[d] = h*h; __syncthreads();
    for (int s = 128; s > 0; s >>= 1) {
        if (d < s) { r1[d] += r1[d+s]; r2[d] += r2[d+s]; }
        __syncthreads();
    }
    float m = r1[0] * (1.f/256.f);
    float var = r2[0] * (1.f/256.f) - m*m;
    x[(size_t)row*256 + d] = (h - m) * rsqrtf(var + 1e-5f) * g[d] + b[d];
}

__global__ void pool_kernel(const float* __restrict__ x, const int* __restrict__ mask,
                            float* __restrict__ pooled) {
    int b = blockIdx.x, d = threadIdx.x;
    float s = 0.f, den = 0.f;
    for (int t = 0; t < 128; ++t) {
        float am = (float)mask[b*128 + t];
        s += x[(size_t)(b*128 + t)*256 + d] * am;
        den += am;
    }
    pooled[b*256 + d] = s / fmaxf(den, 1.0f);
}

// pe[b,j] = dot(pooled[b], W[j]) + bias[j]; one warp per row j; W read exactly once.
__global__ void pe_kernel(const float* __restrict__ pooled, const float* __restrict__ W,
                          const float* __restrict__ bias, float* __restrict__ pe) {
    __shared__ float sp[1024];
    int t = threadIdx.x;
    #pragma unroll
    for (int i = 0; i < 4; ++i) sp[t + i*256] = pooled[t + i*256];
    __syncthreads();
    int warp = t >> 5, lane = t & 31;
    int j = blockIdx.x * 8 + warp;     // row, < 114688
    const float4* w4 = reinterpret_cast<const float4*>(W + (size_t)j * 256);
    float4 w0 = w4[lane];
    float4 w1 = w4[lane + 32];
    int k0 = lane * 4, k1 = (lane + 32) * 4;
    float acc[4];
    #pragma unroll
    for (int b = 0; b < 4; ++b) {
        const float* p = &sp[b*256];
        acc[b] = w0.x*p[k0] + w0.y*p[k0+1] + w0.z*p[k0+2] + w0.w*p[k0+3]
               + w1.x*p[k1] + w1.y*p[k1+1] + w1.z*p[k1+2] + w1.w*p[k1+3];
    }
    #pragma unroll
    for (int b = 0; b < 4; ++b)
        #pragma unroll
        for (int off = 16; off > 0; off >>= 1)
            acc[b] += __shfl_xor_sync(0xFFFFFFFFu, acc[b], off);
    if (lane < 4) pe[(size_t)lane * PEROW + j] = acc[lane] + bias[j];
}

// out[b,i,r,c] = A_base[b,p(i),r,c%64] * sa[p(i)]; source float4 is loop-invariant per thread.
__global__ void write_tileA(const float4* __restrict__ Ab4, const float* __restrict__ scales,
                            float4* __restrict__ out, int nI, int ind4, int mode) {
    int bx = blockIdx.x;
    int r = bx & 15;
    int i = (bx >> 4) % nI;
    int b = (bx >> 4) / nI;
    int p = (mode == 0) ? (i/6)*7 + (i%6) : i*7 + 6;
    float s = scales[2*p];
    float4 v = Ab4[(size_t)(b*224 + p)*256 + r*16 + (threadIdx.x & 15)];
    v.x *= s; v.y *= s; v.z *= s; v.w *= s;
    size_t base = ((size_t)(b*nI + i)*16 + r) * ind4;
    for (int c4 = threadIdx.x; c4 < ind4; c4 += 256)
        __stcs(&out[base + c4], v);
}

// out[b,i,r2,c] = B_base[b,p(i),r2%64,c] * sb[p(i)]; per-thread source float4 loop-invariant.
__global__ void write_tileB(const float4* __restrict__ Bb4, const float* __restrict__ scales,
                            float4* __restrict__ out, int nI, int cnt, int nSplit, int mode) {
    int bx = blockIdx.x;
    int sp = bx % nSplit;
    int i = (bx / nSplit) % nI;
    int b = (bx / nSplit) / nI;
    int p;
    if (mode == 0)      p = (i/3)*7 + (i%3)*3;
    else if (mode == 1) p = (i/2)*7 + 1 + (i%2);
    else                p = (i/2)*7 + 4 + (i%2);
    float s = scales[2*p + 1];
    float4 v = Bb4[(size_t)(b*224 + p)*256 + threadIdx.x];
    v.x *= s; v.y *= s; v.z *= s; v.w *= s;
    size_t base = (size_t)(b*nI + i) * ((size_t)cnt * nSplit) + (size_t)sp * cnt;
    for (int f = threadIdx.x; f < cnt; f += 256)
        __stcs(&out[base + f], v);
}

// ---------------- launch ----------------
extern "C" void kernel_launch(void* const* d_in, const int* in_sizes, int n_in,
                              void* d_out, int out_size) {
    const int*   ids   = (const int*)d_in[0];
    const int*   amask = (const int*)d_in[1];
    const float* E     = (const float*)d_in[2];
    const float* qkvw  = (const float*)d_in[3];
    const float* qkvb  = (const float*)d_in[4];
    const float* ow    = (const float*)d_in[5];
    const float* ob    = (const float*)d_in[6];
    const float* ln1g  = (const float*)d_in[7];
    const float* ln1b  = (const float*)d_in[8];
    const float* f1w   = (const float*)d_in[9];
    const float* f1b   = (const float*)d_in[10];
    const float* f2w   = (const float*)d_in[11];
    const float* f2b   = (const float*)d_in[12];
    const float* ln2g  = (const float*)d_in[13];
    const float* ln2b  = (const float*)d_in[14];
    const float* projw = (const float*)d_in[15];
    const float* projb = (const float*)d_in[16];
    const float* a1w   = (const float*)d_in[17];
    const float* a1b   = (const float*)d_in[18];
    const float* a2w   = (const float*)d_in[19];
    const float* a2b   = (const float*)d_in[20];
    const float* bw1   = (const float*)d_in[21];
    const float* bb1   = (const float*)d_in[22];
    const float* bw2   = (const float*)d_in[23];
    const float* bb2   = (const float*)d_in[24];
    const float* scales= (const float*)d_in[25];

    float* S = nullptr;
    cudaGetSymbolAddress((void**)&S, g_scratch);
    float* x    = S + S_X;
    float* qkv  = S + S_QKV;
    float* attn = S + S_ATTN;
    float* ff1  = S + S_FF1;
    float* tmp  = S + S_TMP;     // scores / residual tmp
    float* pool = S + S_POOL;
    float* pe   = S + S_PE;
    float* dech = S + S_DECH;
    float* Ab   = S + S_AB;
    float* Bb   = S + S_BB;
    float* part = S + S_PART;
    float* out  = (float*)d_out;

    embed_kernel<<<TOK, 64>>>(ids, E, x);

    for (int l = 0; l < 3; ++l) {
        gemm_nt<0><<<dim3(12, 8, 1), 256>>>(x, qkvw + (size_t)l*768*256, qkvb + l*768,
                                            qkv, nullptr, TOK, 768, 256);
        attn_scores<<<dim3(128, 16), 128>>>(qkv, amask, tmp);
        attn_av<<<dim3(128, 16), 64>>>(qkv, tmp, attn);
        gemm_nt<0><<<dim3(4, 8, 1), 256>>>(attn, ow + (size_t)l*256*256, ob + l*256,
                                           tmp, nullptr, TOK, 256, 256);
        add_ln<<<TOK, 256>>>(x, tmp, ln1g + l*256, ln1b + l*256);
        gemm_nt<1><<<dim3(32, 8, 1), 256>>>(x, f1w + (size_t)l*2048*256, f1b + l*2048,
                                            ff1, nullptr, TOK, 2048, 256);
        gemm_nt<0><<<dim3(4, 8, 8), 256>>>(ff1, f2w + (size_t)l*256*2048, nullptr,
                                           nullptr, part, TOK, 256, 2048);
        ksplit_reduce<<<512, 256>>>(part, f2b + l*256, tmp, TOK*256, 256, 8);
        add_ln<<<TOK, 256>>>(x, tmp, ln2g + l*256, ln2b + l*256);
    }

    pool_kernel<<<BSZ, 256>>>(x, amask, pool);
    pe_kernel<<<PEROW/8, 256>>>(pool, projw, projb, pe);

    gemm_nt<2><<<dim3(4, 14, 1), 256>>>(pe, a1w, a1b, dech, nullptr, 896, 256, 512);
    gemm_nt<0><<<dim3(16, 14, 1), 256>>>(dech, a2w, a2b, Ab, nullptr, 896, 1024, 256);
    gemm_nt<2><<<dim3(4, 14, 1), 256>>>(pe, bw1, bb1, dech, nullptr, 896, 256, 512);
    gemm_nt<0><<<dim3(16, 14, 1), 256>>>(dech, bw2, bb2, Bb, nullptr, 896, 1024, 256);

    write_tileA<<<4*192*16, 256>>>((const float4*)Ab, scales, (float4*)out,               192, 4096/4,  0);
    write_tileA<<<4*32*16,  256>>>((const float4*)Ab, scales, (float4*)(out + OFF_AINT),  32,  11008/4, 1);
    write_tileB<<<4*96*4,   256>>>((const float4*)Bb, scales, (float4*)(out + OFF_BHID),  96,  4096,  4, 0);
    write_tileB<<<4*64*2,   256>>>((const float4*)Bb, scales, (float4*)(out + OFF_BKV),   64,  2048,  2, 1);
    write_tileB<<<4*64*4,   256>>>((const float4*)Bb, scales, (float4*)(out + OFF_BINT),  64,  11008, 4, 2);
}

// round 2
// speedup vs baseline: 1.4921x; 1.4921x over previous
#include <cuda_runtime.h>
#include <cuda_bf16.h>
#include <cstdint>
#include <cstddef>

// ---------------- problem constants ----------------
#define BSZ   4
#define SEQ   128
#define TOK   (BSZ*SEQ)        // 512
#define DM    256
#define FF    2048
#define PP    224
#define PED   512
#define PEROW (PP*PED)         // 114688

// output region sizes (floats)
#define SZ_AHID (4LL*192*16*4096)
#define SZ_AINT (4LL*32*16*11008)
#define SZ_BHID (4LL*96*4096*16)
#define SZ_BKV  (4LL*64*1024*16)
#define OFF_AINT (SZ_AHID)
#define OFF_BHID (SZ_AHID+SZ_AINT)
#define OFF_BKV  (OFF_BHID+SZ_BHID)
#define OFF_BINT (OFF_BKV+SZ_BKV)

// ---------------- scratch ----------------
#define S_X     0
#define S_QKV   (S_X    + TOK*DM)
#define S_ATTN  (S_QKV  + TOK*3*DM)
#define S_FF1   (S_ATTN + TOK*DM)
#define S_TMP   (S_FF1  + TOK*FF)
#define S_POOL  (S_TMP  + TOK*DM)
#define S_PE    (S_POOL + BSZ*DM)
#define S_DECH  (S_PE   + BSZ*PEROW)
#define S_AB    (S_DECH + 896*DM)
#define S_BB    (S_AB   + 896*1024)
#define S_PART  (S_BB   + 896*1024)
#define S_TOTAL (S_PART + 4*TOK*DM)

__device__ float g_scratch[S_TOTAL];

// ---------------- helpers ----------------
__device__ __forceinline__ unsigned f2tf(float x) {
    unsigned u; asm("cvt.rna.tf32.f32 %0, %1;" : "=r"(u) : "f"(x)); return u;
}
__device__ __forceinline__ void mma_tf32(float* d, const unsigned* a, const unsigned* b) {
    asm volatile("mma.sync.aligned.m16n8k8.row.col.f32.tf32.tf32.f32 "
        "{%0,%1,%2,%3}, {%4,%5,%6,%7}, {%8,%9}, {%0,%1,%2,%3};\n"
        : "+f"(d[0]), "+f"(d[1]), "+f"(d[2]), "+f"(d[3])
        : "r"(a[0]), "r"(a[1]), "r"(a[2]), "r"(a[3]), "r"(b[0]), "r"(b[1]));
}

// ---------------- kernels ----------------

__global__ void embed_kernel(const int* __restrict__ ids, const float* __restrict__ E,
                             float* __restrict__ x) {
    int tok = blockIdx.x;
    int t = threadIdx.x;
    int id = ids[tok];
    reinterpret_cast<float4*>(x)[tok*64 + t] =
        reinterpret_cast<const float4*>(E)[(size_t)id*64 + t];
}

// C[m,n] = epi( sum_k X[m,k]*W[n,k] + bias[n] ), tf32 tensor cores.
// BM=BN=64, BK=32, 128 threads (4 warps, 32x32 warp tile).
// gridDim.z>1 => split-K partials into Cpart (no bias/epi).
#define SK 36   // smem row stride (floats): bank = 4*r + c, conflict-free frags
template<int EPI>
__global__ __launch_bounds__(128) void gemm_mma(
        const float* __restrict__ X, const float* __restrict__ W,
        const float* __restrict__ bias, float* __restrict__ C,
        float* __restrict__ Cpart, int M, int N, int K) {
    __shared__ unsigned Xs[2][64][SK];
    __shared__ unsigned Ws[2][64][SK];
    int tid = threadIdx.x;
    int lane = tid & 31, wid = tid >> 5;
    int wm = wid >> 1, wn = wid & 1;
    int r = lane >> 2, cq = lane & 3;
    int m0 = blockIdx.y * 64, n0 = blockIdx.x * 64;
    int kchunk = K / gridDim.z;
    int kbeg = blockIdx.z * kchunk;
    int nk = kchunk >> 5;

    int lrow = tid >> 3;              // 0..15
    int lkq  = (tid & 7) * 4;         // 0,4,..28
    const float* xg = X + (size_t)(m0 + lrow) * K + kbeg + lkq;
    const float* wg = W + (size_t)(n0 + lrow) * K + kbeg + lkq;

    float acc[2][4][4] = {};

    // preload tile 0
    {
        #pragma unroll
        for (int v = 0; v < 4; ++v) {
            float4 a = *reinterpret_cast<const float4*>(xg + (size_t)v*16*K);
            float4 b = *reinterpret_cast<const float4*>(wg + (size_t)v*16*K);
            uint4 ua = {f2tf(a.x), f2tf(a.y), f2tf(a.z), f2tf(a.w)};
            uint4 ub = {f2tf(b.x), f2tf(b.y), f2tf(b.z), f2tf(b.w)};
            *reinterpret_cast<uint4*>(&Xs[0][lrow + v*16][lkq]) = ua;
            *reinterpret_cast<uint4*>(&Ws[0][lrow + v*16][lkq]) = ub;
        }
    }
    __syncthreads();

    int buf = 0;
    for (int kt = 0; kt < nk; ++kt) {
        float4 px[4], pw[4];
        if (kt + 1 < nk) {
            #pragma unroll
            for (int v = 0; v < 4; ++v) {
                px[v] = *reinterpret_cast<const float4*>(xg + (size_t)v*16*K + (kt+1)*32);
                pw[v] = *reinterpret_cast<const float4*>(wg + (size_t)v*16*K + (kt+1)*32);
            }
        }
        #pragma unroll
        for (int ks = 0; ks < 4; ++ks) {
            unsigned af[2][4], bf[4][2];
            #pragma unroll
            for (int mt = 0; mt < 2; ++mt) {
                int mr = wm*32 + mt*16 + r;
                af[mt][0] = Xs[buf][mr][ks*8 + cq];
                af[mt][1] = Xs[buf][mr + 8][ks*8 + cq];
                af[mt][2] = Xs[buf][mr][ks*8 + cq + 4];
                af[mt][3] = Xs[buf][mr + 8][ks*8 + cq + 4];
            }
            #pragma unroll
            for (int nt = 0; nt < 4; ++nt) {
                int nr = wn*32 + nt*8 + r;
                bf[nt][0] = Ws[buf][nr][ks*8 + cq];
                bf[nt][1] = Ws[buf][nr][ks*8 + cq + 4];
            }
            #pragma unroll
            for (int mt = 0; mt < 2; ++mt)
                #pragma unroll
                for (int nt = 0; nt < 4; ++nt)
                    mma_tf32(acc[mt][nt], af[mt], bf[nt]);
        }
        if (kt + 1 < nk) {
            #pragma unroll
            for (int v = 0; v < 4; ++v) {
                uint4 ua = {f2tf(px[v].x), f2tf(px[v].y), f2tf(px[v].z), f2tf(px[v].w)};
                uint4 ub = {f2tf(pw[v].x), f2tf(pw[v].y), f2tf(pw[v].z), f2tf(pw[v].w)};
                *reinterpret_cast<uint4*>(&Xs[buf^1][lrow + v*16][lkq]) = ua;
                *reinterpret_cast<uint4*>(&Ws[buf^1][lrow + v*16][lkq]) = ub;
            }
            __syncthreads();
            buf ^= 1;
        }
    }

    if (gridDim.z == 1) {
        #pragma unroll
        for (int mt = 0; mt < 2; ++mt) {
            #pragma unroll
            for (int nt = 0; nt < 4; ++nt) {
                int m = m0 + wm*32 + mt*16 + r;
                int n = n0 + wn*32 + nt*8 + cq*2;
                #pragma unroll
                for (int half = 0; half < 2; ++half) {
                    int mm = m + half*8;
                    float v0 = acc[mt][nt][half*2+0] + bias[n];
                    float v1 = acc[mt][nt][half*2+1] + bias[n+1];
                    if (EPI == 1) { v0 = fmaxf(v0, 0.f); v1 = fmaxf(v1, 0.f); }
                    if (EPI == 2) {
                        v0 = 0.5f*v0*(1.f + erff(v0*0.70710678118654752f));
                        v1 = 0.5f*v1*(1.f + erff(v1*0.70710678118654752f));
                    }
                    *reinterpret_cast<float2*>(&C[(size_t)mm*N + n]) = make_float2(v0, v1);
                }
            }
        }
    } else {
        float* P = Cpart + (size_t)blockIdx.z * M * N;
        #pragma unroll
        for (int mt = 0; mt < 2; ++mt)
            #pragma unroll
            for (int nt = 0; nt < 4; ++nt) {
                int m = m0 + wm*32 + mt*16 + r;
                int n = n0 + wn*32 + nt*8 + cq*2;
                #pragma unroll
                for (int half = 0; half < 2; ++half)
                    *reinterpret_cast<float2*>(&P[(size_t)(m + half*8)*N + n]) =
                        make_float2(acc[mt][nt][half*2], acc[mt][nt][half*2+1]);
            }
    }
}

__global__ void ksplit_reduce(const float* __restrict__ P, const float* __restrict__ bias,
                              float* __restrict__ C, int MN, int N, int parts) {
    int i = blockIdx.x * 256 + threadIdx.x;
    if (i >= MN) return;
    float s = bias[i % N];
    for (int p = 0; p < parts; ++p) s += P[(size_t)p * MN + i];
    C[i] = s;
}

// Fused attention: block = (q-chunk of 32, b*4+h). 256 threads.
// smem: Qs[32][68], Ks[128][68], Vs[128][68], Ps[32][129]
#define AQ_OFF 0
#define AK_OFF (32*68)
#define AV_OFF (AK_OFF + 128*68)
#define AP_OFF (AV_OFF + 128*68)
#define ATT_SMEM ((AP_OFF + 32*129)*4)
__global__ void attn_fused(const float* __restrict__ qkv, const int* __restrict__ mask,
                           float* __restrict__ o) {
    extern __shared__ float sm[];
    int tid = threadIdx.x;
    int qc = blockIdx.x;               // 0..3
    int bh = blockIdx.y;               // 0..15
    int b = bh >> 2, h = bh & 3;

    const float4* src = reinterpret_cast<const float4*>(qkv);
    // load Q (32 rows), K, V (128 rows each) for this head
    #pragma unroll
    for (int it = 0; it < 2; ++it) {
        int e = it*256 + tid;          // 512
        int row = e >> 4, d4 = e & 15;
        sm[AQ_OFF + row*68 + d4*4 + 0] = 0.f; // placeholder to keep layout; overwritten below
        float4 v = src[((size_t)(b*128 + qc*32 + row)*768 + h*64) / 4 + d4];
        *reinterpret_cast<float4*>(&sm[AQ_OFF + row*68 + d4*4]) = v;
    }
    #pragma unroll
    for (int it = 0; it < 8; ++it) {
        int e = it*256 + tid;          // 2048
        int row = e >> 4, d4 = e & 15;
        float4 k = src[((size_t)(b*128 + row)*768 + 256 + h*64) / 4 + d4];
        float4 v = src[((size_t)(b*128 + row)*768 + 512 + h*64) / 4 + d4];
        *reinterpret_cast<float4*>(&sm[AK_OFF + row*68 + d4*4]) = k;
        *reinterpret_cast<float4*>(&sm[AV_OFF + row*68 + d4*4]) = v;
    }
    __syncthreads();

    int q = tid >> 3;                  // 0..31
    int kb = tid & 7;                  // 0..7
    // scores: each thread owns k = kb + 8*i, i=0..15
    float s[16];
    #pragma unroll
    for (int i = 0; i < 16; ++i) {
        int k = kb + 8*i;
        const float4* qp = reinterpret_cast<const float4*>(&sm[AQ_OFF + q*68]);
        const float4* kp = reinterpret_cast<const float4*>(&sm[AK_OFF + k*68]);
        float acc = 0.f;
        #pragma unroll
        for (int d4 = 0; d4 < 16; ++d4) {
            float4 a = qp[d4], c = kp[d4];
            acc += a.x*c.x + a.y*c.y + a.z*c.z + a.w*c.w;
        }
        acc *= 0.125f;
        if (mask[b*128 + k] == 0) acc = -1e9f;
        s[i] = acc;
    }
    float mx = s[0];
    #pragma unroll
    for (int i = 1; i < 16; ++i) mx = fmaxf(mx, s[i]);
    #pragma unroll
    for (int off = 1; off < 8; off <<= 1)
        mx = fmaxf(mx, __shfl_xor_sync(0xFFFFFFFFu, mx, off));
    float sum = 0.f;
    #pragma unroll
    for (int i = 0; i < 16; ++i) { s[i] = __expf(s[i] - mx); sum += s[i]; }
    #pragma unroll
    for (int off = 1; off < 8; off <<= 1)
        sum += __shfl_xor_sync(0xFFFFFFFFu, sum, off);
    float inv = 1.f / sum;
    #pragma unroll
    for (int i = 0; i < 16; ++i)
        sm[AP_OFF + q*129 + kb + 8*i] = s[i] * inv;
    __syncthreads();

    // AV: thread owns (q, 8 dims at dg*8)
    int dg = tid & 7;
    float acc[8] = {};
    const float* Pr = &sm[AP_OFF + q*129];
    #pragma unroll 4
    for (int k = 0; k < 128; ++k) {
        float p = Pr[k];
        const float4* vp = reinterpret_cast<const float4*>(&sm[AV_OFF + k*68 + dg*8]);
        float4 v0 = vp[0], v1 = vp[1];
        acc[0] += p*v0.x; acc[1] += p*v0.y; acc[2] += p*v0.z; acc[3] += p*v0.w;
        acc[4] += p*v1.x; acc[5] += p*v1.y; acc[6] += p*v1.z; acc[7] += p*v1.w;
    }
    size_t orow = (size_t)(b*128 + qc*32 + q)*256 + h*64 + dg*8;
    *reinterpret_cast<float4*>(&o[orow])     = make_float4(acc[0], acc[1], acc[2], acc[3]);
    *reinterpret_cast<float4*>(&o[orow + 4]) = make_float4(acc[4], acc[5], acc[6], acc[7]);
}

__global__ void add_ln(float* __restrict__ x, const float* __restrict__ t_,
                       const float* __restrict__ g, const float* __restrict__ b) {
    int row = blockIdx.x;
    int d = threadIdx.x;
    __shared__ float r1[256], r2[256];
    float h = x[(size_t)row*256 + d] + t_[(size_t)row*256 + d];
    r1[d] = h; r2[d] = h*h; __syncthreads();
    for (int s = 128; s > 0; s >>= 1) {
        if (d < s) { r1[d] += r1[d+s]; r2[d] += r2[d+s]; }
        __syncthreads();
    }
    float m = r1[0] * (1.f/256.f);
    float var = r2[0] * (1.f/256.f) - m*m;
    x[(size_t)row*256 + d] = (h - m) * rsqrtf(var + 1e-5f) * g[d] + b[d];
}

__global__ void pool_kernel(const float* __restrict__ x, const int* __restrict__ mask,
                            float* __restrict__ pooled) {
    int b = blockIdx.x, d = threadIdx.x;
    float s = 0.f, den = 0.f;
    for (int t = 0; t < 128; ++t) {
        float am = (float)mask[b*128 + t];
        s += x[(size_t)(b*128 + t)*256 + d] * am;
        den += am;
    }
    pooled[b*256 + d] = s / fmaxf(den, 1.0f);
}

__global__ void pe_kernel(const float* __restrict__ pooled, const float* __restrict__ W,
                          const float* __restrict__ bias, float* __restrict__ pe) {
    __shared__ float sp[1024];
    int t = threadIdx.x;
    #pragma unroll
    for (int i = 0; i < 4; ++i) sp[t + i*256] = pooled[t + i*256];
    __syncthreads();
    int warp = t >> 5, lane = t & 31;
    int j = blockIdx.x * 8 + warp;
    const float4* w4 = reinterpret_cast<const float4*>(W + (size_t)j * 256);
    float4 w0 = w4[lane];
    float4 w1 = w4[lane + 32];
    int k0 = lane * 4, k1 = (lane + 32) * 4;
    float acc[4];
    #pragma unroll
    for (int b = 0; b < 4; ++b) {
        const float* p = &sp[b*256];
        acc[b] = w0.x*p[k0] + w0.y*p[k0+1] + w0.z*p[k0+2] + w0.w*p[k0+3]
               + w1.x*p[k1] + w1.y*p[k1+1] + w1.z*p[k1+2] + w1.w*p[k1+3];
    }
    #pragma unroll
    for (int b = 0; b < 4; ++b)
        #pragma unroll
        for (int off = 16; off > 0; off >>= 1)
            acc[b] += __shfl_xor_sync(0xFFFFFFFFu, acc[b], off);
    if (lane < 4) pe[(size_t)lane * PEROW + j] = acc[lane] + bias[j];
}

__global__ void write_tileA(const float4* __restrict__ Ab4, const float* __restrict__ scales,
                            float4* __restrict__ out, int nI, int ind4, int mode) {
    int bx = blockIdx.x;
    int r = bx & 15;
    int i = (bx >> 4) % nI;
    int b = (bx >> 4) / nI;
    int p = (mode == 0) ? (i/6)*7 + (i%6) : i*7 + 6;
    float s = scales[2*p];
    float4 v = Ab4[(size_t)(b*224 + p)*256 + r*16 + (threadIdx.x & 15)];
    v.x *= s; v.y *= s; v.z *= s; v.w *= s;
    size_t base = ((size_t)(b*nI + i)*16 + r) * ind4;
    for (int c4 = threadIdx.x; c4 < ind4; c4 += 256)
        __stcs(&out[base + c4], v);
}

__global__ void write_tileB(const float4* __restrict__ Bb4, const float* __restrict__ scales,
                            float4* __restrict__ out, int nI, int cnt, int nSplit, int mode) {
    int bx = blockIdx.x;
    int sp = bx % nSplit;
    int i = (bx / nSplit) % nI;
    int b = (bx / nSplit) / nI;
    int p;
    if (mode == 0)      p = (i/3)*7 + (i%3)*3;
    else if (mode == 1) p = (i/2)*7 + 1 + (i%2);
    else                p = (i/2)*7 + 4 + (i%2);
    float s = scales[2*p + 1];
    float4 v = Bb4[(size_t)(b*224 + p)*256 + threadIdx.x];
    v.x *= s; v.y *= s; v.z *= s; v.w *= s;
    size_t base = (size_t)(b*nI + i) * ((size_t)cnt * nSplit) + (size_t)sp * cnt;
    for (int f = threadIdx.x; f < cnt; f += 256)
        __stcs(&out[base + f], v);
}

// ---------------- launch ----------------
extern "C" void kernel_launch(void* const* d_in, const int* in_sizes, int n_in,
                              void* d_out, int out_size) {
    const int*   ids   = (const int*)d_in[0];
    const int*   amask = (const int*)d_in[1];
    const float* E     = (const float*)d_in[2];
    const float* qkvw  = (const float*)d_in[3];
    const float* qkvb  = (const float*)d_in[4];
    const float* ow    = (const float*)d_in[5];
    const float* ob    = (const float*)d_in[6];
    const float* ln1g  = (const float*)d_in[7];
    const float* ln1b  = (const float*)d_in[8];
    const float* f1w   = (const float*)d_in[9];
    const float* f1b   = (const float*)d_in[10];
    const float* f2w   = (const float*)d_in[11];
    const float* f2b   = (const float*)d_in[12];
    const float* ln2g  = (const float*)d_in[13];
    const float* ln2b  = (const float*)d_in[14];
    const float* projw = (const float*)d_in[15];
    const float* projb = (const float*)d_in[16];
    const float* a1w   = (const float*)d_in[17];
    const float* a1b   = (const float*)d_in[18];
    const float* a2w   = (const float*)d_in[19];
    const float* a2b   = (const float*)d_in[20];
    const float* bw1   = (const float*)d_in[21];
    const float* bb1   = (const float*)d_in[22];
    const float* bw2   = (const float*)d_in[23];
    const float* bb2   = (const float*)d_in[24];
    const float* scales= (const float*)d_in[25];

    static int init = 0;
    if (!init) {
        cudaFuncSetAttribute(attn_fused, cudaFuncAttributeMaxDynamicSharedMemorySize, ATT_SMEM);
        init = 1;
    }

    float* S = nullptr;
    cudaGetSymbolAddress((void**)&S, g_scratch);
    float* x    = S + S_X;
    float* qkv  = S + S_QKV;
    float* attn = S + S_ATTN;
    float* ff1  = S + S_FF1;
    float* tmp  = S + S_TMP;
    float* pool = S + S_POOL;
    float* pe   = S + S_PE;
    float* dech = S + S_DECH;
    float* Ab   = S + S_AB;
    float* Bb   = S + S_BB;
    float* part = S + S_PART;
    float* out  = (float*)d_out;

    embed_kernel<<<TOK, 64>>>(ids, E, x);

    for (int l = 0; l < 3; ++l) {
        gemm_mma<0><<<dim3(12, 8, 1), 128>>>(x, qkvw + (size_t)l*768*256, qkvb + l*768,
                                             qkv, nullptr, TOK, 768, 256);
        attn_fused<<<dim3(4, 16), 256, ATT_SMEM>>>(qkv, amask, attn);
        gemm_mma<0><<<dim3(4, 8, 1), 128>>>(attn, ow + (size_t)l*256*256, ob + l*256,
                                            tmp, nullptr, TOK, 256, 256);
        add_ln<<<TOK, 256>>>(x, tmp, ln1g + l*256, ln1b + l*256);
        gemm_mma<1><<<dim3(32, 8, 1), 128>>>(x, f1w + (size_t)l*2048*256, f1b + l*2048,
                                             ff1, nullptr, TOK, 2048, 256);
        gemm_mma<0><<<dim3(4, 8, 4), 128>>>(ff1, f2w + (size_t)l*256*2048, nullptr,
                                            nullptr, part, TOK, 256, 2048);
        ksplit_reduce<<<512, 256>>>(part, f2b + l*256, tmp, TOK*256, 256, 4);
        add_ln<<<TOK, 256>>>(x, tmp, ln2g + l*256, ln2b + l*256);
    }

    pool_kernel<<<BSZ, 256>>>(x, amask, pool);
    pe_kernel<<<PEROW/8, 256>>>(pool, projw, projb, pe);

    gemm_mma<2><<<dim3(4, 14, 1), 128>>>(pe, a1w, a1b, dech, nullptr, 896, 256, 512);
    gemm_mma<0><<<dim3(16, 14, 1), 128>>>(dech, a2w, a2b, Ab, nullptr, 896, 1024, 256);
    gemm_mma<2><<<dim3(4, 14, 1), 128>>>(pe, bw1, bb1, dech, nullptr, 896, 256, 512);
    gemm_mma<0><<<dim3(16, 14, 1), 128>>>(dech, bw2, bb2, Bb, nullptr, 896, 1024, 256);

    write_tileA<<<4*192*16, 256>>>((const float4*)Ab, scales, (float4*)out,               192, 4096/4,  0);
    write_tileA<<<4*32*16,  256>>>((const float4*)Ab, scales, (float4*)(out + OFF_AINT),  32,  11008/4, 1);
    write_tileB<<<4*96*4,   256>>>((const float4*)Bb, scales, (float4*)(out + OFF_BHID),  96,  4096,  4, 0);
    write_tileB<<<4*64*2,   256>>>((const float4*)Bb, scales, (float4*)(out + OFF_BKV),   64,  2048,  2, 1);
    write_tileB<<<4*64*4,   256>>>((const float4*)Bb, scales, (float4*)(out + OFF_BINT),  64,  11008, 4, 2);
}

// round 3
// speedup vs baseline: 1.5780x; 1.0575x over previous
#include <cuda_runtime.h>
#include <cuda_bf16.h>
#include <cstdint>
#include <cstddef>

// ---------------- problem constants ----------------
#define BSZ   4
#define SEQ   128
#define TOK   (BSZ*SEQ)        // 512
#define DM    256
#define FF    2048
#define PP    224
#define PED   512
#define PEROW (PP*PED)         // 114688

// output region sizes (floats)
#define SZ_AHID (4LL*192*16*4096)
#define SZ_AINT (4LL*32*16*11008)
#define SZ_BHID (4LL*96*4096*16)
#define SZ_BKV  (4LL*64*1024*16)
#define OFF_AINT (SZ_AHID)
#define OFF_BHID (SZ_AHID+SZ_AINT)
#define OFF_BKV  (OFF_BHID+SZ_BHID)
#define OFF_BINT (OFF_BKV+SZ_BKV)

// ---------------- scratch ----------------
#define S_X     0
#define S_QKV   (S_X    + TOK*DM)
#define S_ATTN  (S_QKV  + TOK*3*DM)
#define S_FF1   (S_ATTN + TOK*DM)
#define S_POOL  (S_FF1  + TOK*FF)
#define S_PE    (S_POOL + BSZ*DM)
#define S_DECHA (S_PE   + BSZ*PEROW)
#define S_DECHB (S_DECHA + 896*DM)
#define S_AB    (S_DECHB + 896*DM)
#define S_BB    (S_AB   + 896*1024)
#define S_PART  (S_BB   + 896*1024)
#define S_TOTAL (S_PART + 4*TOK*DM)

__device__ float g_scratch[S_TOTAL];

// ---------------- helpers ----------------
__device__ __forceinline__ unsigned f2tf(float x) {
    unsigned u; asm("cvt.rna.tf32.f32 %0, %1;" : "=r"(u) : "f"(x)); return u;
}
__device__ __forceinline__ void mma_tf32(float* d, const unsigned* a, const unsigned* b) {
    asm volatile("mma.sync.aligned.m16n8k8.row.col.f32.tf32.tf32.f32 "
        "{%0,%1,%2,%3}, {%4,%5,%6,%7}, {%8,%9}, {%0,%1,%2,%3};\n"
        : "+f"(d[0]), "+f"(d[1]), "+f"(d[2]), "+f"(d[3])
        : "r"(a[0]), "r"(a[1]), "r"(a[2]), "r"(a[3]), "r"(b[0]), "r"(b[1]));
}

// ---------------- kernels ----------------

__global__ void embed_kernel(const int* __restrict__ ids, const float* __restrict__ E,
                             float* __restrict__ x) {
    int tok = blockIdx.x;
    int t = threadIdx.x;
    int id = ids[tok];
    reinterpret_cast<float4*>(x)[tok*64 + t] =
        reinterpret_cast<const float4*>(E)[(size_t)id*64 + t];
}

// C[m,n] = epi( sum_k X[m,k]*W[n,k] + bias[n] ), tf32 tensor cores.
// BM=BN=64, BK=32, 256 threads (8 warps, 16x32 warp tile).
// BATCH=1: blockIdx.z selects problem set {X,W,bias,C} vs {X2,W2,bias2,C2}.
// BATCH=0 && gridDim.z>1: split-K partials into Cpart (no bias/epi).
#define SK 36   // smem row stride (words): bank = (4r+c) conflict-free
template<int EPI, int BATCH>
__global__ __launch_bounds__(256) void gemm_mma(
        const float* __restrict__ X, const float* __restrict__ W,
        const float* __restrict__ bias, float* __restrict__ C,
        float* __restrict__ Cpart,
        const float* __restrict__ X2, const float* __restrict__ W2,
        const float* __restrict__ bias2, float* __restrict__ C2,
        int M, int N, int K) {
    __shared__ unsigned Xs[2][64][SK];
    __shared__ unsigned Ws[2][64][SK];
    int tid = threadIdx.x;
    int lane = tid & 31, wid = tid >> 5;
    int wm = wid & 3, wn = wid >> 2;
    int r = lane >> 2, cq = lane & 3;
    int m0 = blockIdx.y * 64, n0 = blockIdx.x * 64;
    int kbeg, nk;
    if (BATCH) {
        if (blockIdx.z) { X = X2; W = W2; bias = bias2; C = C2; }
        kbeg = 0; nk = K >> 5;
    } else {
        int kchunk = K / gridDim.z;
        kbeg = blockIdx.z * kchunk;
        nk = kchunk >> 5;
    }

    int lrow = tid >> 3;              // 0..31
    int lkq  = (tid & 7) * 4;
    const float* xg = X + (size_t)(m0 + lrow) * K + kbeg + lkq;
    const float* wg = W + (size_t)(n0 + lrow) * K + kbeg + lkq;

    float acc[4][4] = {};

    #pragma unroll
    for (int v = 0; v < 2; ++v) {
        float4 a = *reinterpret_cast<const float4*>(xg + (size_t)v*32*K);
        float4 b = *reinterpret_cast<const float4*>(wg + (size_t)v*32*K);
        uint4 ua = {f2tf(a.x), f2tf(a.y), f2tf(a.z), f2tf(a.w)};
        uint4 ub = {f2tf(b.x), f2tf(b.y), f2tf(b.z), f2tf(b.w)};
        *reinterpret_cast<uint4*>(&Xs[0][lrow + v*32][lkq]) = ua;
        *reinterpret_cast<uint4*>(&Ws[0][lrow + v*32][lkq]) = ub;
    }
    __syncthreads();

    int buf = 0;
    for (int kt = 0; kt < nk; ++kt) {
        float4 px[2], pw[2];
        if (kt + 1 < nk) {
            #pragma unroll
            for (int v = 0; v < 2; ++v) {
                px[v] = *reinterpret_cast<const float4*>(xg + (size_t)v*32*K + (kt+1)*32);
                pw[v] = *reinterpret_cast<const float4*>(wg + (size_t)v*32*K + (kt+1)*32);
            }
        }
        #pragma unroll
        for (int ks = 0; ks < 4; ++ks) {
            unsigned af[4];
            int mr = wm*16 + r;
            af[0] = Xs[buf][mr][ks*8 + cq];
            af[1] = Xs[buf][mr + 8][ks*8 + cq];
            af[2] = Xs[buf][mr][ks*8 + cq + 4];
            af[3] = Xs[buf][mr + 8][ks*8 + cq + 4];
            #pragma unroll
            for (int nt = 0; nt < 4; ++nt) {
                unsigned bf[2];
                int nr = wn*32 + nt*8 + r;
                bf[0] = Ws[buf][nr][ks*8 + cq];
                bf[1] = Ws[buf][nr][ks*8 + cq + 4];
                mma_tf32(acc[nt], af, bf);
            }
        }
        if (kt + 1 < nk) {
            #pragma unroll
            for (int v = 0; v < 2; ++v) {
                uint4 ua = {f2tf(px[v].x), f2tf(px[v].y), f2tf(px[v].z), f2tf(px[v].w)};
                uint4 ub = {f2tf(pw[v].x), f2tf(pw[v].y), f2tf(pw[v].z), f2tf(pw[v].w)};
                *reinterpret_cast<uint4*>(&Xs[buf^1][lrow + v*32][lkq]) = ua;
                *reinterpret_cast<uint4*>(&Ws[buf^1][lrow + v*32][lkq]) = ub;
            }
            __syncthreads();
            buf ^= 1;
        }
    }

    int m = m0 + wm*16 + r;
    if (!BATCH && gridDim.z > 1) {
        float* P = Cpart + (size_t)blockIdx.z * M * N;
        #pragma unroll
        for (int nt = 0; nt < 4; ++nt) {
            int n = n0 + wn*32 + nt*8 + cq*2;
            #pragma unroll
            for (int half = 0; half < 2; ++half)
                *reinterpret_cast<float2*>(&P[(size_t)(m + half*8)*N + n]) =
                    make_float2(acc[nt][half*2], acc[nt][half*2+1]);
        }
    } else {
        #pragma unroll
        for (int nt = 0; nt < 4; ++nt) {
            int n = n0 + wn*32 + nt*8 + cq*2;
            #pragma unroll
            for (int half = 0; half < 2; ++half) {
                float v0 = acc[nt][half*2+0] + bias[n];
                float v1 = acc[nt][half*2+1] + bias[n+1];
                if (EPI == 1) { v0 = fmaxf(v0, 0.f); v1 = fmaxf(v1, 0.f); }
                if (EPI == 2) {
                    v0 = 0.5f*v0*(1.f + erff(v0*0.70710678118654752f));
                    v1 = 0.5f*v1*(1.f + erff(v1*0.70710678118654752f));
                }
                *reinterpret_cast<float2*>(&C[(size_t)(m + half*8)*N + n]) = make_float2(v0, v1);
            }
        }
    }
}

// sum split-K partials + bias + residual, then LayerNorm; writes x in place.
__global__ void ksplit_ln(const float* __restrict__ P, const float* __restrict__ bias,
                          float* __restrict__ x, const float* __restrict__ g,
                          const float* __restrict__ b, int parts) {
    int row = blockIdx.x, d = threadIdx.x;
    __shared__ float r1[256], r2[256];
    size_t idx = (size_t)row*256 + d;
    float s = bias[d];
    for (int p = 0; p < parts; ++p) s += P[(size_t)p*TOK*DM + idx];
    float h = x[idx] + s;
    r1[d] = h; r2[d] = h*h; __syncthreads();
    for (int st = 128; st > 0; st >>= 1) {
        if (d < st) { r1[d] += r1[d+st]; r2[d] += r2[d+st]; }
        __syncthreads();
    }
    float m = r1[0] * (1.f/256.f);
    float var = r2[0] * (1.f/256.f) - m*m;
    x[idx] = (h - m) * rsqrtf(var + 1e-5f) * g[d] + b[d];
}

// Fused attention: block = (q-chunk of 32, b*4+h). 256 threads.
#define AQ_OFF 0
#define AK_OFF (32*68)
#define AV_OFF (AK_OFF + 128*68)
#define AP_OFF (AV_OFF + 128*68)
#define ATT_SMEM ((AP_OFF + 32*129)*4)
__global__ void attn_fused(const float* __restrict__ qkv, const int* __restrict__ mask,
                           float* __restrict__ o) {
    extern __shared__ float sm[];
    int tid = threadIdx.x;
    int qc = blockIdx.x;
    int bh = blockIdx.y;
    int b = bh >> 2, h = bh & 3;

    const float4* src = reinterpret_cast<const float4*>(qkv);
    #pragma unroll
    for (int it = 0; it < 2; ++it) {
        int e = it*256 + tid;
        int row = e >> 4, d4 = e & 15;
        float4 v = src[((size_t)(b*128 + qc*32 + row)*768 + h*64) / 4 + d4];
        *reinterpret_cast<float4*>(&sm[AQ_OFF + row*68 + d4*4]) = v;
    }
    #pragma unroll
    for (int it = 0; it < 8; ++it) {
        int e = it*256 + tid;
        int row = e >> 4, d4 = e & 15;
        float4 k = src[((size_t)(b*128 + row)*768 + 256 + h*64) / 4 + d4];
        float4 v = src[((size_t)(b*128 + row)*768 + 512 + h*64) / 4 + d4];
        *reinterpret_cast<float4*>(&sm[AK_OFF + row*68 + d4*4]) = k;
        *reinterpret_cast<float4*>(&sm[AV_OFF + row*68 + d4*4]) = v;
    }
    __syncthreads();

    int q = tid >> 3;
    int kb = tid & 7;
    float s[16];
    #pragma unroll
    for (int i = 0; i < 16; ++i) {
        int k = kb + 8*i;
        const float4* qp = reinterpret_cast<const float4*>(&sm[AQ_OFF + q*68]);
        const float4* kp = reinterpret_cast<const float4*>(&sm[AK_OFF + k*68]);
        float acc = 0.f;
        #pragma unroll
        for (int d4 = 0; d4 < 16; ++d4) {
            float4 a = qp[d4], c = kp[d4];
            acc += a.x*c.x + a.y*c.y + a.z*c.z + a.w*c.w;
        }
        acc *= 0.125f;
        if (mask[b*128 + k] == 0) acc = -1e9f;
        s[i] = acc;
    }
    float mx = s[0];
    #pragma unroll
    for (int i = 1; i < 16; ++i) mx = fmaxf(mx, s[i]);
    #pragma unroll
    for (int off = 1; off < 8; off <<= 1)
        mx = fmaxf(mx, __shfl_xor_sync(0xFFFFFFFFu, mx, off));
    float sum = 0.f;
    #pragma unroll
    for (int i = 0; i < 16; ++i) { s[i] = __expf(s[i] - mx); sum += s[i]; }
    #pragma unroll
    for (int off = 1; off < 8; off <<= 1)
        sum += __shfl_xor_sync(0xFFFFFFFFu, sum, off);
    float inv = 1.f / sum;
    #pragma unroll
    for (int i = 0; i < 16; ++i)
        sm[AP_OFF + q*129 + kb + 8*i] = s[i] * inv;
    __syncthreads();

    int dg = tid & 7;
    float acc[8] = {};
    const float* Pr = &sm[AP_OFF + q*129];
    #pragma unroll 4
    for (int k = 0; k < 128; ++k) {
        float p = Pr[k];
        const float4* vp = reinterpret_cast<const float4*>(&sm[AV_OFF + k*68 + dg*8]);
        float4 v0 = vp[0], v1 = vp[1];
        acc[0] += p*v0.x; acc[1] += p*v0.y; acc[2] += p*v0.z; acc[3] += p*v0.w;
        acc[4] += p*v1.x; acc[5] += p*v1.y; acc[6] += p*v1.z; acc[7] += p*v1.w;
    }
    size_t orow = (size_t)(b*128 + qc*32 + q)*256 + h*64 + dg*8;
    *reinterpret_cast<float4*>(&o[orow])     = make_float4(acc[0], acc[1], acc[2], acc[3]);
    *reinterpret_cast<float4*>(&o[orow + 4]) = make_float4(acc[4], acc[5], acc[6], acc[7]);
}

__global__ void pool_kernel(const float* __restrict__ x, const int* __restrict__ mask,
                            float* __restrict__ pooled) {
    int b = blockIdx.x, d = threadIdx.x;
    float s = 0.f, den = 0.f;
    for (int t = 0; t < 128; ++t) {
        float am = (float)mask[b*128 + t];
        s += x[(size_t)(b*128 + t)*256 + d] * am;
        den += am;
    }
    pooled[b*256 + d] = s / fmaxf(den, 1.0f);
}

__global__ void pe_kernel(const float* __restrict__ pooled, const float* __restrict__ W,
                          const float* __restrict__ bias, float* __restrict__ pe) {
    __shared__ float sp[1024];
    int t = threadIdx.x;
    #pragma unroll
    for (int i = 0; i < 4; ++i) sp[t + i*256] = pooled[t + i*256];
    __syncthreads();
    int warp = t >> 5, lane = t & 31;
    int j = blockIdx.x * 8 + warp;
    const float4* w4 = reinterpret_cast<const float4*>(W + (size_t)j * 256);
    float4 w0 = w4[lane];
    float4 w1 = w4[lane + 32];
    int k0 = lane * 4, k1 = (lane + 32) * 4;
    float acc[4];
    #pragma unroll
    for (int b = 0; b < 4; ++b) {
        const float* p = &sp[b*256];
        acc[b] = w0.x*p[k0] + w0.y*p[k0+1] + w0.z*p[k0+2] + w0.w*p[k0+3]
               + w1.x*p[k1] + w1.y*p[k1+1] + w1.z*p[k1+2] + w1.w*p[k1+3];
    }
    #pragma unroll
    for (int b = 0; b < 4; ++b)
        #pragma unroll
        for (int off = 16; off > 0; off >>= 1)
            acc[b] += __shfl_xor_sync(0xFFFFFFFFu, acc[b], off);
    if (lane < 4) pe[(size_t)lane * PEROW + j] = acc[lane] + bias[j];
}

__global__ void write_tileA(const float4* __restrict__ Ab4, const float* __restrict__ scales,
                            float4* __restrict__ out, int nI, int ind4, int mode) {
    int bx = blockIdx.x;
    int r = bx & 15;
    int i = (bx >> 4) % nI;
    int b = (bx >> 4) / nI;
    int p = (mode == 0) ? (i/6)*7 + (i%6) : i*7 + 6;
    float s = scales[2*p];
    float4 v = Ab4[(size_t)(b*224 + p)*256 + r*16 + (threadIdx.x & 15)];
    v.x *= s; v.y *= s; v.z *= s; v.w *= s;
    size_t base = ((size_t)(b*nI + i)*16 + r) * ind4;
    for (int c4 = threadIdx.x; c4 < ind4; c4 += 256)
        __stcs(&out[base + c4], v);
}

__global__ void write_tileB(const float4* __restrict__ Bb4, const float* __restrict__ scales,
                            float4* __restrict__ out, int nI, int cnt, int nSplit, int mode) {
    int bx = blockIdx.x;
    int sp = bx % nSplit;
    int i = (bx / nSplit) % nI;
    int b = (bx / nSplit) / nI;
    int p;
    if (mode == 0)      p = (i/3)*7 + (i%3)*3;
    else if (mode == 1) p = (i/2)*7 + 1 + (i%2);
    else                p = (i/2)*7 + 4 + (i%2);
    float s = scales[2*p + 1];
    float4 v = Bb4[(size_t)(b*224 + p)*256 + threadIdx.x];
    v.x *= s; v.y *= s; v.z *= s; v.w *= s;
    size_t base = (size_t)(b*nI + i) * ((size_t)cnt * nSplit) + (size_t)sp * cnt;
    for (int f = threadIdx.x; f < cnt; f += 256)
        __stcs(&out[base + f], v);
}

// ---------------- launch ----------------
extern "C" void kernel_launch(void* const* d_in, const int* in_sizes, int n_in,
                              void* d_out, int out_size) {
    const int*   ids   = (const int*)d_in[0];
    const int*   amask = (const int*)d_in[1];
    const float* E     = (const float*)d_in[2];
    const float* qkvw  = (const float*)d_in[3];
    const float* qkvb  = (const float*)d_in[4];
    const float* ow    = (const float*)d_in[5];
    const float* ob    = (const float*)d_in[6];
    const float* ln1g  = (const float*)d_in[7];
    const float* ln1b  = (const float*)d_in[8];
    const float* f1w   = (const float*)d_in[9];
    const float* f1b   = (const float*)d_in[10];
    const float* f2w   = (const float*)d_in[11];
    const float* f2b   = (const float*)d_in[12];
    const float* ln2g  = (const float*)d_in[13];
    const float* ln2b  = (const float*)d_in[14];
    const float* projw = (const float*)d_in[15];
    const float* projb = (const float*)d_in[16];
    const float* a1w   = (const float*)d_in[17];
    const float* a1b   = (const float*)d_in[18];
    const float* a2w   = (const float*)d_in[19];
    const float* a2b   = (const float*)d_in[20];
    const float* bw1   = (const float*)d_in[21];
    const float* bb1   = (const float*)d_in[22];
    const float* bw2   = (const float*)d_in[23];
    const float* bb2   = (const float*)d_in[24];
    const float* scales= (const float*)d_in[25];

    static int init = 0;
    if (!init) {
        cudaFuncSetAttribute(attn_fused, cudaFuncAttributeMaxDynamicSharedMemorySize, ATT_SMEM);
        init = 1;
    }

    float* S = nullptr;
    cudaGetSymbolAddress((void**)&S, g_scratch);
    float* x     = S + S_X;
    float* qkv   = S + S_QKV;
    float* attn  = S + S_ATTN;
    float* ff1   = S + S_FF1;
    float* pool  = S + S_POOL;
    float* pe    = S + S_PE;
    float* dechA = S + S_DECHA;
    float* dechB = S + S_DECHB;
    float* Ab    = S + S_AB;
    float* Bb    = S + S_BB;
    float* part  = S + S_PART;
    float* out   = (float*)d_out;

    embed_kernel<<<TOK, 64>>>(ids, E, x);

    for (int l = 0; l < 3; ++l) {
        gemm_mma<0,0><<<dim3(12, 8, 1), 256>>>(x, qkvw + (size_t)l*768*256, qkvb + l*768,
                                               qkv, nullptr, nullptr, nullptr, nullptr, nullptr,
                                               TOK, 768, 256);
        attn_fused<<<dim3(4, 16), 256, ATT_SMEM>>>(qkv, amask, attn);
        gemm_mma<0,0><<<dim3(4, 8, 4), 256>>>(attn, ow + (size_t)l*256*256, nullptr,
                                              nullptr, part, nullptr, nullptr, nullptr, nullptr,
                                              TOK, 256, 256);
        ksplit_ln<<<TOK, 256>>>(part, ob + l*256, x, ln1g + l*256, ln1b + l*256, 4);
        gemm_mma<1,0><<<dim3(32, 8, 1), 256>>>(x, f1w + (size_t)l*2048*256, f1b + l*2048,
                                               ff1, nullptr, nullptr, nullptr, nullptr, nullptr,
                                               TOK, 2048, 256);
        gemm_mma<0,0><<<dim3(4, 8, 4), 256>>>(ff1, f2w + (size_t)l*256*2048, nullptr,
                                              nullptr, part, nullptr, nullptr, nullptr, nullptr,
                                              TOK, 256, 2048);
        ksplit_ln<<<TOK, 256>>>(part, f2b + l*256, x, ln2g + l*256, ln2b + l*256, 4);
    }

    pool_kernel<<<BSZ, 256>>>(x, amask, pool);
    pe_kernel<<<PEROW/8, 256>>>(pool, projw, projb, pe);

    gemm_mma<2,1><<<dim3(4, 14, 2), 256>>>(pe, a1w, a1b, dechA, nullptr,
                                           pe, bw1, bb1, dechB, 896, 256, 512);
    gemm_mma<0,1><<<dim3(16, 14, 2), 256>>>(dechA, a2w, a2b, Ab, nullptr,
                                            dechB, bw2, bb2, Bb, 896, 1024, 256);

    write_tileA<<<4*192*16, 256>>>((const float4*)Ab, scales, (float4*)out,               192, 4096/4,  0);
    write_tileA<<<4*32*16,  256>>>((const float4*)Ab, scales, (float4*)(out + OFF_AINT),  32,  11008/4, 1);
    write_tileB<<<4*96*4,   256>>>((const float4*)Bb, scales, (float4*)(out + OFF_BHID),  96,  4096,  4, 0);
    write_tileB<<<4*64*2,   256>>>((const float4*)Bb, scales, (float4*)(out + OFF_BKV),   64,  2048,  2, 1);
    write_tileB<<<4*64*4,   256>>>((const float4*)Bb, scales, (float4*)(out + OFF_BINT),  64,  11008, 4, 2);
}

// round 4
// speedup vs baseline: 1.6760x; 1.0621x over previous
#include <cuda_runtime.h>
#include <cuda_bf16.h>
#include <cstdint>
#include <cstddef>

// ---------------- problem constants ----------------
#define BSZ   4
#define SEQ   128
#define TOK   (BSZ*SEQ)        // 512
#define DM    256
#define FF    2048
#define PP    224
#define PED   512
#define PEROW (PP*PED)         // 114688

// output region sizes (floats)
#define SZ_AHID (4LL*192*16*4096)
#define SZ_AINT (4LL*32*16*11008)
#define SZ_BHID (4LL*96*4096*16)
#define SZ_BKV  (4LL*64*1024*16)
#define OFF_AINT (SZ_AHID)
#define OFF_BHID (SZ_AHID+SZ_AINT)
#define OFF_BKV  (OFF_BHID+SZ_BHID)
#define OFF_BINT (OFF_BKV+SZ_BKV)

// ---------------- scratch ----------------
#define S_X     0
#define S_QKV   (S_X    + TOK*DM)
#define S_ATTN  (S_QKV  + TOK*3*DM)
#define S_FF1   (S_ATTN + TOK*DM)
#define S_POOL  (S_FF1  + TOK*FF)
#define S_PE    (S_POOL + BSZ*DM)
#define S_DECHA (S_PE   + BSZ*PEROW)
#define S_DECHB (S_DECHA + 896*DM)
#define S_AB    (S_DECHB + 896*DM)
#define S_BB    (S_AB   + 896*1024)
#define S_PART  (S_BB   + 896*1024)
#define S_TOTAL (S_PART + 4*TOK*DM)

__device__ float g_scratch[S_TOTAL];

// ---------------- helpers ----------------
__device__ __forceinline__ unsigned f2tf(float x) {
    unsigned u; asm("cvt.rna.tf32.f32 %0, %1;" : "=r"(u) : "f"(x)); return u;
}
__device__ __forceinline__ void mma_tf32(float* d, const unsigned* a, const unsigned* b) {
    asm volatile("mma.sync.aligned.m16n8k8.row.col.f32.tf32.tf32.f32 "
        "{%0,%1,%2,%3}, {%4,%5,%6,%7}, {%8,%9}, {%0,%1,%2,%3};\n"
        : "+f"(d[0]), "+f"(d[1]), "+f"(d[2]), "+f"(d[3])
        : "r"(a[0]), "r"(a[1]), "r"(a[2]), "r"(a[3]), "r"(b[0]), "r"(b[1]));
}

// ---------------- kernels ----------------

__global__ void embed_kernel(const int* __restrict__ ids, const float* __restrict__ E,
                             float* __restrict__ x) {
    int tok = blockIdx.x;
    int t = threadIdx.x;
    int id = ids[tok];
    reinterpret_cast<float4*>(x)[tok*64 + t] =
        reinterpret_cast<const float4*>(E)[(size_t)id*64 + t];
}

// C[m,n] = epi( sum_k X[m,k]*W[n,k] + bias[n] ), tf32 tensor cores.
// BM=BN=32, BK=32, 128 threads (4 warps, 16x16 warp tile).
// BATCH=1: blockIdx.z selects problem set A vs B.
// BATCH=0 && gridDim.z>1: split-K partials into Cpart (no bias/epi).
#define SK 36
template<int EPI, int BATCH>
__global__ __launch_bounds__(128) void gemm32(
        const float* __restrict__ X, const float* __restrict__ W,
        const float* __restrict__ bias, float* __restrict__ C,
        float* __restrict__ Cpart,
        const float* __restrict__ X2, const float* __restrict__ W2,
        const float* __restrict__ bias2, float* __restrict__ C2,
        int M, int N, int K) {
    __shared__ unsigned Xs[2][32][SK];
    __shared__ unsigned Ws[2][32][SK];
    int tid = threadIdx.x;
    int lane = tid & 31, wid = tid >> 5;
    int wm = wid & 1, wn = wid >> 1;
    int r = lane >> 2, cq = lane & 3;
    int m0 = blockIdx.y * 32, n0 = blockIdx.x * 32;
    int kbeg, nk;
    if (BATCH) {
        if (blockIdx.z) { X = X2; W = W2; bias = bias2; C = C2; }
        kbeg = 0; nk = K >> 5;
    } else {
        int kchunk = K / gridDim.z;
        kbeg = blockIdx.z * kchunk;
        nk = kchunk >> 5;
    }

    int lrow = tid >> 2;              // 0..31
    int lkq  = (tid & 3) * 4;         // 0,4,8,12
    const float* xg = X + (size_t)(m0 + lrow) * K + kbeg + lkq;
    const float* wg = W + (size_t)(n0 + lrow) * K + kbeg + lkq;

    float acc[2][4] = {};

    {
        float4 a0 = *reinterpret_cast<const float4*>(xg);
        float4 a1 = *reinterpret_cast<const float4*>(xg + 16);
        float4 b0 = *reinterpret_cast<const float4*>(wg);
        float4 b1 = *reinterpret_cast<const float4*>(wg + 16);
        uint4 ua0 = {f2tf(a0.x), f2tf(a0.y), f2tf(a0.z), f2tf(a0.w)};
        uint4 ua1 = {f2tf(a1.x), f2tf(a1.y), f2tf(a1.z), f2tf(a1.w)};
        uint4 ub0 = {f2tf(b0.x), f2tf(b0.y), f2tf(b0.z), f2tf(b0.w)};
        uint4 ub1 = {f2tf(b1.x), f2tf(b1.y), f2tf(b1.z), f2tf(b1.w)};
        *reinterpret_cast<uint4*>(&Xs[0][lrow][lkq])      = ua0;
        *reinterpret_cast<uint4*>(&Xs[0][lrow][lkq + 16]) = ua1;
        *reinterpret_cast<uint4*>(&Ws[0][lrow][lkq])      = ub0;
        *reinterpret_cast<uint4*>(&Ws[0][lrow][lkq + 16]) = ub1;
    }
    __syncthreads();

    int buf = 0;
    for (int kt = 0; kt < nk; ++kt) {
        float4 pa0, pa1, pb0, pb1;
        if (kt + 1 < nk) {
            pa0 = *reinterpret_cast<const float4*>(xg + (kt+1)*32);
            pa1 = *reinterpret_cast<const float4*>(xg + (kt+1)*32 + 16);
            pb0 = *reinterpret_cast<const float4*>(wg + (kt+1)*32);
            pb1 = *reinterpret_cast<const float4*>(wg + (kt+1)*32 + 16);
        }
        #pragma unroll
        for (int ks = 0; ks < 4; ++ks) {
            unsigned af[4];
            int mr = wm*16 + r;
            af[0] = Xs[buf][mr][ks*8 + cq];
            af[1] = Xs[buf][mr + 8][ks*8 + cq];
            af[2] = Xs[buf][mr][ks*8 + cq + 4];
            af[3] = Xs[buf][mr + 8][ks*8 + cq + 4];
            #pragma unroll
            for (int nt = 0; nt < 2; ++nt) {
                unsigned bf[2];
                int nr = wn*16 + nt*8 + r;
                bf[0] = Ws[buf][nr][ks*8 + cq];
                bf[1] = Ws[buf][nr][ks*8 + cq + 4];
                mma_tf32(acc[nt], af, bf);
            }
        }
        if (kt + 1 < nk) {
            uint4 ua0 = {f2tf(pa0.x), f2tf(pa0.y), f2tf(pa0.z), f2tf(pa0.w)};
            uint4 ua1 = {f2tf(pa1.x), f2tf(pa1.y), f2tf(pa1.z), f2tf(pa1.w)};
            uint4 ub0 = {f2tf(pb0.x), f2tf(pb0.y), f2tf(pb0.z), f2tf(pb0.w)};
            uint4 ub1 = {f2tf(pb1.x), f2tf(pb1.y), f2tf(pb1.z), f2tf(pb1.w)};
            *reinterpret_cast<uint4*>(&Xs[buf^1][lrow][lkq])      = ua0;
            *reinterpret_cast<uint4*>(&Xs[buf^1][lrow][lkq + 16]) = ua1;
            *reinterpret_cast<uint4*>(&Ws[buf^1][lrow][lkq])      = ub0;
            *reinterpret_cast<uint4*>(&Ws[buf^1][lrow][lkq + 16]) = ub1;
            __syncthreads();
            buf ^= 1;
        }
    }

    int m = m0 + wm*16 + r;
    if (!BATCH && gridDim.z > 1) {
        float* P = Cpart + (size_t)blockIdx.z * M * N;
        #pragma unroll
        for (int nt = 0; nt < 2; ++nt) {
            int n = n0 + wn*16 + nt*8 + cq*2;
            #pragma unroll
            for (int half = 0; half < 2; ++half)
                *reinterpret_cast<float2*>(&P[(size_t)(m + half*8)*N + n]) =
                    make_float2(acc[nt][half*2], acc[nt][half*2+1]);
        }
    } else {
        #pragma unroll
        for (int nt = 0; nt < 2; ++nt) {
            int n = n0 + wn*16 + nt*8 + cq*2;
            #pragma unroll
            for (int half = 0; half < 2; ++half) {
                float v0 = acc[nt][half*2+0] + bias[n];
                float v1 = acc[nt][half*2+1] + bias[n+1];
                if (EPI == 1) { v0 = fmaxf(v0, 0.f); v1 = fmaxf(v1, 0.f); }
                if (EPI == 2) {
                    v0 = 0.5f*v0*(1.f + erff(v0*0.70710678118654752f));
                    v1 = 0.5f*v1*(1.f + erff(v1*0.70710678118654752f));
                }
                *reinterpret_cast<float2*>(&C[(size_t)(m + half*8)*N + n]) = make_float2(v0, v1);
            }
        }
    }
}

// sum split-K partials + bias + residual, then LayerNorm; writes x in place.
__global__ void ksplit_ln(const float* __restrict__ P, const float* __restrict__ bias,
                          float* __restrict__ x, const float* __restrict__ g,
                          const float* __restrict__ b, int parts) {
    int row = blockIdx.x, d = threadIdx.x;
    __shared__ float r1[256], r2[256];
    size_t idx = (size_t)row*256 + d;
    float s = bias[d];
    for (int p = 0; p < parts; ++p) s += P[(size_t)p*TOK*DM + idx];
    float h = x[idx] + s;
    r1[d] = h; r2[d] = h*h; __syncthreads();
    for (int st = 128; st > 0; st >>= 1) {
        if (d < st) { r1[d] += r1[d+st]; r2[d] += r2[d+st]; }
        __syncthreads();
    }
    float m = r1[0] * (1.f/256.f);
    float var = r2[0] * (1.f/256.f) - m*m;
    x[idx] = (h - m) * rsqrtf(var + 1e-5f) * g[d] + b[d];
}

// Fused attention: block = (q-chunk of 16, b*4+h). 256 threads, grid (8,16).
#define AQ_OFF 0
#define AK_OFF (16*68)
#define AV_OFF (AK_OFF + 128*68)
#define AP_OFF (AV_OFF + 128*68)
#define ATT_SMEM ((AP_OFF + 16*129)*4)
__global__ void attn_fused(const float* __restrict__ qkv, const int* __restrict__ mask,
                           float* __restrict__ o) {
    extern __shared__ float sm[];
    int tid = threadIdx.x;
    int qc = blockIdx.x;               // 0..7
    int bh = blockIdx.y;               // 0..15
    int b = bh >> 2, h = bh & 3;

    const float4* src = reinterpret_cast<const float4*>(qkv);
    {
        int row = tid >> 4, d4 = tid & 15;
        float4 v = src[((size_t)(b*128 + qc*16 + row)*768 + h*64) / 4 + d4];
        *reinterpret_cast<float4*>(&sm[AQ_OFF + row*68 + d4*4]) = v;
    }
    #pragma unroll
    for (int it = 0; it < 8; ++it) {
        int e = it*256 + tid;
        int row = e >> 4, d4 = e & 15;
        float4 k = src[((size_t)(b*128 + row)*768 + 256 + h*64) / 4 + d4];
        float4 v = src[((size_t)(b*128 + row)*768 + 512 + h*64) / 4 + d4];
        *reinterpret_cast<float4*>(&sm[AK_OFF + row*68 + d4*4]) = k;
        *reinterpret_cast<float4*>(&sm[AV_OFF + row*68 + d4*4]) = v;
    }
    __syncthreads();

    int q = tid >> 4;                  // 0..15
    int kb = tid & 15;                 // 0..15
    float s[8];
    #pragma unroll
    for (int i = 0; i < 8; ++i) {
        int k = kb + 16*i;
        const float4* qp = reinterpret_cast<const float4*>(&sm[AQ_OFF + q*68]);
        const float4* kp = reinterpret_cast<const float4*>(&sm[AK_OFF + k*68]);
        float acc = 0.f;
        #pragma unroll
        for (int d4 = 0; d4 < 16; ++d4) {
            float4 a = qp[d4], c = kp[d4];
            acc += a.x*c.x + a.y*c.y + a.z*c.z + a.w*c.w;
        }
        acc *= 0.125f;
        if (mask[b*128 + k] == 0) acc = -1e9f;
        s[i] = acc;
    }
    float mx = s[0];
    #pragma unroll
    for (int i = 1; i < 8; ++i) mx = fmaxf(mx, s[i]);
    #pragma unroll
    for (int off = 1; off < 16; off <<= 1)
        mx = fmaxf(mx, __shfl_xor_sync(0xFFFFFFFFu, mx, off));
    float sum = 0.f;
    #pragma unroll
    for (int i = 0; i < 8; ++i) { s[i] = __expf(s[i] - mx); sum += s[i]; }
    #pragma unroll
    for (int off = 1; off < 16; off <<= 1)
        sum += __shfl_xor_sync(0xFFFFFFFFu, sum, off);
    float inv = 1.f / sum;
    #pragma unroll
    for (int i = 0; i < 8; ++i)
        sm[AP_OFF + q*129 + kb + 16*i] = s[i] * inv;
    __syncthreads();

    // AV: thread owns (q, 4 dims at dg*4)
    int dg = tid & 15;
    float4 acc4 = {0.f, 0.f, 0.f, 0.f};
    const float* Pr = &sm[AP_OFF + q*129];
    #pragma unroll 4
    for (int k = 0; k < 128; ++k) {
        float p = Pr[k];
        float4 v = *reinterpret_cast<const float4*>(&sm[AV_OFF + k*68 + dg*4]);
        acc4.x += p*v.x; acc4.y += p*v.y; acc4.z += p*v.z; acc4.w += p*v.w;
    }
    size_t orow = (size_t)(b*128 + qc*16 + q)*256 + h*64 + dg*4;
    *reinterpret_cast<float4*>(&o[orow]) = acc4;
}

__global__ void pool_kernel(const float* __restrict__ x, const int* __restrict__ mask,
                            float* __restrict__ pooled) {
    int b = blockIdx.x, d = threadIdx.x;
    float s = 0.f, den = 0.f;
    for (int t = 0; t < 128; ++t) {
        float am = (float)mask[b*128 + t];
        s += x[(size_t)(b*128 + t)*256 + d] * am;
        den += am;
    }
    pooled[b*256 + d] = s / fmaxf(den, 1.0f);
}

__global__ void pe_kernel(const float* __restrict__ pooled, const float* __restrict__ W,
                          const float* __restrict__ bias, float* __restrict__ pe) {
    __shared__ float sp[1024];
    int t = threadIdx.x;
    #pragma unroll
    for (int i = 0; i < 4; ++i) sp[t + i*256] = pooled[t + i*256];
    __syncthreads();
    int warp = t >> 5, lane = t & 31;
    int j = blockIdx.x * 8 + warp;
    const float4* w4 = reinterpret_cast<const float4*>(W + (size_t)j * 256);
    float4 w0 = w4[lane];
    float4 w1 = w4[lane + 32];
    int k0 = lane * 4, k1 = (lane + 32) * 4;
    float acc[4];
    #pragma unroll
    for (int b = 0; b < 4; ++b) {
        const float* p = &sp[b*256];
        acc[b] = w0.x*p[k0] + w0.y*p[k0+1] + w0.z*p[k0+2] + w0.w*p[k0+3]
               + w1.x*p[k1] + w1.y*p[k1+1] + w1.z*p[k1+2] + w1.w*p[k1+3];
    }
    #pragma unroll
    for (int b = 0; b < 4; ++b)
        #pragma unroll
        for (int off = 16; off > 0; off >>= 1)
            acc[b] += __shfl_xor_sync(0xFFFFFFFFu, acc[b], off);
    if (lane < 4) pe[(size_t)lane * PEROW + j] = acc[lane] + bias[j];
}

// ---- unified writer: 5 regions in one launch ----
#define NB_A0 12288   // 4*192*16
#define NB_A1 2048    // 4*32*16
#define NB_B0 1536    // 4*96*4
#define NB_B1 512     // 4*64*2
#define NB_B2 1024    // 4*64*4
__device__ __forceinline__ void wr_A(const float4* Ab4, const float* scales,
                                     float4* out, int bx, int nI, int ind4, int mode,
                                     int tid) {
    int r = bx & 15;
    int i = (bx >> 4) % nI;
    int b = (bx >> 4) / nI;
    int p = (mode == 0) ? (i/6)*7 + (i%6) : i*7 + 6;
    float s = scales[2*p];
    float4 v = Ab4[(size_t)(b*224 + p)*256 + r*16 + (tid & 15)];
    v.x *= s; v.y *= s; v.z *= s; v.w *= s;
    size_t base = ((size_t)(b*nI + i)*16 + r) * ind4;
    for (int c4 = tid; c4 < ind4; c4 += 256)
        __stcs(&out[base + c4], v);
}
__device__ __forceinline__ void wr_B(const float4* Bb4, const float* scales,
                                     float4* out, int bx, int nI, int cnt, int nSplit,
                                     int mode, int tid) {
    int sp = bx % nSplit;
    int i = (bx / nSplit) % nI;
    int b = (bx / nSplit) / nI;
    int p;
    if (mode == 0)      p = (i/3)*7 + (i%3)*3;
    else if (mode == 1) p = (i/2)*7 + 1 + (i%2);
    else                p = (i/2)*7 + 4 + (i%2);
    float s = scales[2*p + 1];
    float4 v = Bb4[(size_t)(b*224 + p)*256 + tid];
    v.x *= s; v.y *= s; v.z *= s; v.w *= s;
    size_t base = (size_t)(b*nI + i) * ((size_t)cnt * nSplit) + (size_t)sp * cnt;
    for (int f = tid; f < cnt; f += 256)
        __stcs(&out[base + f], v);
}
__global__ __launch_bounds__(256) void write_all(
        const float4* __restrict__ Ab4, const float4* __restrict__ Bb4,
        const float* __restrict__ scales, float* __restrict__ outf) {
    int bx = blockIdx.x;
    int tid = threadIdx.x;
    if (bx < NB_A0) {
        wr_A(Ab4, scales, (float4*)outf, bx, 192, 4096/4, 0, tid); return;
    }
    bx -= NB_A0;
    if (bx < NB_A1) {
        wr_A(Ab4, scales, (float4*)(outf + OFF_AINT), bx, 32, 11008/4, 1, tid); return;
    }
    bx -= NB_A1;
    if (bx < NB_B0) {
        wr_B(Bb4, scales, (float4*)(outf + OFF_BHID), bx, 96, 4096, 4, 0, tid); return;
    }
    bx -= NB_B0;
    if (bx < NB_B1) {
        wr_B(Bb4, scales, (float4*)(outf + OFF_BKV), bx, 64, 2048, 2, 1, tid); return;
    }
    bx -= NB_B1;
    wr_B(Bb4, scales, (float4*)(outf + OFF_BINT), bx, 64, 11008, 4, 2, tid);
}

// ---------------- launch ----------------
extern "C" void kernel_launch(void* const* d_in, const int* in_sizes, int n_in,
                              void* d_out, int out_size) {
    const int*   ids   = (const int*)d_in[0];
    const int*   amask = (const int*)d_in[1];
    const float* E     = (const float*)d_in[2];
    const float* qkvw  = (const float*)d_in[3];
    const float* qkvb  = (const float*)d_in[4];
    const float* ow    = (const float*)d_in[5];
    const float* ob    = (const float*)d_in[6];
    const float* ln1g  = (const float*)d_in[7];
    const float* ln1b  = (const float*)d_in[8];
    const float* f1w   = (const float*)d_in[9];
    const float* f1b   = (const float*)d_in[10];
    const float* f2w   = (const float*)d_in[11];
    const float* f2b   = (const float*)d_in[12];
    const float* ln2g  = (const float*)d_in[13];
    const float* ln2b  = (const float*)d_in[14];
    const float* projw = (const float*)d_in[15];
    const float* projb = (const float*)d_in[16];
    const float* a1w   = (const float*)d_in[17];
    const float* a1b   = (const float*)d_in[18];
    const float* a2w   = (const float*)d_in[19];
    const float* a2b   = (const float*)d_in[20];
    const float* bw1   = (const float*)d_in[21];
    const float* bb1   = (const float*)d_in[22];
    const float* bw2   = (const float*)d_in[23];
    const float* bb2   = (const float*)d_in[24];
    const float* scales= (const float*)d_in[25];

    static int init = 0;
    if (!init) {
        cudaFuncSetAttribute(attn_fused, cudaFuncAttributeMaxDynamicSharedMemorySize, ATT_SMEM);
        init = 1;
    }

    float* S = nullptr;
    cudaGetSymbolAddress((void**)&S, g_scratch);
    float* x     = S + S_X;
    float* qkv   = S + S_QKV;
    float* attn  = S + S_ATTN;
    float* ff1   = S + S_FF1;
    float* pool  = S + S_POOL;
    float* pe    = S + S_PE;
    float* dechA = S + S_DECHA;
    float* dechB = S + S_DECHB;
    float* Ab    = S + S_AB;
    float* Bb    = S + S_BB;
    float* part  = S + S_PART;
    float* out   = (float*)d_out;

    embed_kernel<<<TOK, 64>>>(ids, E, x);

    for (int l = 0; l < 3; ++l) {
        gemm32<0,0><<<dim3(24, 16, 1), 128>>>(x, qkvw + (size_t)l*768*256, qkvb + l*768,
                                              qkv, nullptr, nullptr, nullptr, nullptr, nullptr,
                                              TOK, 768, 256);
        attn_fused<<<dim3(8, 16), 256, ATT_SMEM>>>(qkv, amask, attn);
        gemm32<0,0><<<dim3(8, 16, 2), 128>>>(attn, ow + (size_t)l*256*256, nullptr,
                                             nullptr, part, nullptr, nullptr, nullptr, nullptr,
                                             TOK, 256, 256);
        ksplit_ln<<<TOK, 256>>>(part, ob + l*256, x, ln1g + l*256, ln1b + l*256, 2);
        gemm32<1,0><<<dim3(64, 16, 1), 128>>>(x, f1w + (size_t)l*2048*256, f1b + l*2048,
                                              ff1, nullptr, nullptr, nullptr, nullptr, nullptr,
                                              TOK, 2048, 256);
        gemm32<0,0><<<dim3(8, 16, 4), 128>>>(ff1, f2w + (size_t)l*256*2048, nullptr,
                                             nullptr, part, nullptr, nullptr, nullptr, nullptr,
                                             TOK, 256, 2048);
        ksplit_ln<<<TOK, 256>>>(part, f2b + l*256, x, ln2g + l*256, ln2b + l*256, 4);
    }

    pool_kernel<<<BSZ, 256>>>(x, amask, pool);
    pe_kernel<<<PEROW/8, 256>>>(pool, projw, projb, pe);

    gemm32<2,1><<<dim3(8, 28, 2), 128>>>(pe, a1w, a1b, dechA, nullptr,
                                         pe, bw1, bb1, dechB, 896, 256, 512);
    gemm32<0,1><<<dim3(32, 28, 2), 128>>>(dechA, a2w, a2b, Ab, nullptr,
                                          dechB, bw2, bb2, Bb, 896, 1024, 256);

    write_all<<<NB_A0 + NB_A1 + NB_B0 + NB_B1 + NB_B2, 256>>>(
        (const float4*)Ab, (const float4*)Bb, scales, out);
}